// round 16
// baseline (speedup 1.0000x reference)
#include <cuda_runtime.h>
#include <cuda_fp16.h>
#include <cstdint>

// ---------------- problem dims ----------------
#define DIM_B 32
#define DIM_P 8
#define DIM_K 8
#define DIM_D 768
#define DIM_G 20000
#define TOPK_N 200

constexpr int BP  = DIM_B * DIM_P;   // 256
constexpr int KD  = DIM_K * DIM_D;   // 6144
constexpr int MQ  = BP * DIM_K;      // 2048
constexpr int DD  = DIM_D * DIM_D;
constexpr float SCALE  = 0.036084391824351615f; // 768^-0.5
constexpr float MARGIN = 1.5e-3f;
constexpr int   BANDCAP = 256;
constexpr int   KT384 = KD / 16;     // 384 k16-tiles

// ---------------- scratch (device globals; no alloc) ----------------
__device__ float g_w[DIM_K];
__device__ float g_cqT[DIM_D * MQ];                       // cQ transposed (768 x 2048)
__device__ float g_W2p[4 * DD];                           // W2 split-K partials
__device__ float g_W2 [DD];                               // Wq^T @ Wk
__device__ float g_P3a[MQ * DIM_D];                       // PROJ partial (k-half 0)
__device__ float g_P3b[MQ * DIM_D];                       // PROJ partial (k-half 1)
__device__ float g_vk[DIM_D];                             // bk @ Wq
__device__ float g_bv[DIM_D];                             // bq @ Wk
__device__ float g_bqk;                                   // bq . bk
__device__ float g_A [MQ * DIM_D];                        // fp32 exact A (linear)
__device__ __align__(16) uint32_t g_A0[MQ * DIM_D / 2];   // fp16 plane of A, fragment-packed
__device__ float g_rowbias[BP];

// ---------------- helpers ----------------
__device__ __forceinline__ uint32_t smem_u32(const void* p) {
    uint32_t a;
    asm("{ .reg .u64 t; cvta.to.shared.u64 t, %1; cvt.u32.u64 %0, t; }" : "=r"(a) : "l"(p));
    return a;
}
__device__ __forceinline__ void mma_hf(float* c, const uint32_t* a, uint32_t b0, uint32_t b1) {
    asm volatile("mma.sync.aligned.m16n8k16.row.col.f32.f16.f16.f32 "
                 "{%0,%1,%2,%3}, {%4,%5,%6,%7}, {%8,%9}, {%0,%1,%2,%3};"
                 : "+f"(c[0]), "+f"(c[1]), "+f"(c[2]), "+f"(c[3])
                 : "r"(a[0]), "r"(a[1]), "r"(a[2]), "r"(a[3]), "r"(b0), "r"(b1));
}
__device__ __forceinline__ void cpa16(uint32_t dst, const void* src) {
    asm volatile("cp.async.cg.shared.global [%0], [%1], 16;" :: "r"(dst), "l"(src));
}
__device__ __forceinline__ unsigned pack_hf2(float a, float b) {
    __half2 h = __floats2half2_rn(a, b);
    return *reinterpret_cast<unsigned*>(&h);
}
__device__ __forceinline__ unsigned f2key(float f) {
    unsigned u = __float_as_uint(f);
    return (u & 0x80000000u) ? ~u : (u | 0x80000000u);
}
__device__ __forceinline__ float key2f(unsigned k) {
    unsigned u = (k & 0x80000000u) ? (k ^ 0x80000000u) : ~k;
    return __uint_as_float(u);
}
__device__ __forceinline__ unsigned long long pk2(float x, float y) {
    unsigned long long r;
    asm("mov.b64 %0, {%1,%2};" : "=l"(r) : "f"(x), "f"(y));
    return r;
}
__device__ __forceinline__ void fma2(unsigned long long& d, unsigned long long a, unsigned long long b) {
    asm("fma.rn.f32x2 %0, %1, %2, %0;" : "+l"(d) : "l"(a), "l"(b));
}
__device__ __forceinline__ float2 upk2(unsigned long long v) {
    float2 r;
    asm("mov.b64 {%0,%1}, %2;" : "=f"(r.x), "=f"(r.y) : "l"(v));
    return r;
}

// ================== main GEMM: C(256x20000) = fp16(A).fp16(GF)^T — M-split, 3 CTAs/SM ==================
// Grid (2, 313): x = M-half (adjacent CTAs share B in L2), y = N-tile.
// CTA tile 128(M) x 64(N); 8 warps = 2M x 4N (warp tile 64x16); k-chunk 32; single-product fp16.
// Full cp.async pipeline (3 stages, 2-chunk lookahead); B raw fp32 staged, converted SMEM->SMEM.
constexpr int BNN = 64, KCH = 32;
constexpr int NCH = KD / KCH;                 // 192 chunks
constexpr int NTY = (DIM_G + BNN - 1) / BNN;  // 313
constexpr int OF_A  = 0;                      // 8KB: [mt 0..7][kt 0..1] x 512B
constexpr int OF_BR = 8192;                   // raw B: 64 rows x 144B = 9216B
constexpr int BR_STRIDE = 144;
constexpr int OF_BF = 17408;                  // fp16 B frags: 4KB
constexpr int STG_SZ = 21504;
constexpr int STAGES = 3;
constexpr int SMEM_MAIN = STAGES * STG_SZ;    // 64512 -> 3 CTAs/SM

__global__ void __launch_bounds__(256, 3)
mma_main(const uint32_t* __restrict__ A0p,
         const float* __restrict__ GF, float* __restrict__ C)
{
    extern __shared__ char sm[];
    const uint32_t sb = smem_u32(sm);
    const int tid = threadIdx.x;
    const int mhalf = blockIdx.x;
    const int n0 = blockIdx.y * BNN;

    // ---- A loader: thread covers 32B of the 8KB chunk (2 cp.async) ----
    const int a_mt  = tid >> 5;            // local m-tile 0..7
    const int a_ktl = (tid >> 4) & 1;
    const int a_in  = (tid & 15) * 32;
    const char* srcA = (const char*)A0p
        + (size_t)((mhalf * 8 + a_mt) * KT384 + a_ktl) * 512 + a_in;
    const uint32_t dstA = (uint32_t)(OF_A + tid * 32);

    // ---- B loader: row gr (0..63), octet bq (0..3) ----
    const int gr = tid >> 2, bq = tid & 3;
    const int ggl = n0 + gr;
    const bool gok = ggl < DIM_G;
    const float* Gsrc = GF + (size_t)(gok ? ggl : 0) * KD + bq * 8;
    const uint32_t dstBR = (uint32_t)(OF_BR + gr * BR_STRIDE + bq * 32);
    const int gg8 = gr & 7;
    const uint32_t dstBF = (uint32_t)(OF_BF + ((gr >> 3) * 2 + (bq >> 1)) * 256 + (bq & 1) * 4);

    // ---- warp fragment coords: 2M x 4N ----
    const int L = tid & 31, wid = tid >> 5;
    const int wm = wid & 1, wn = wid >> 1;
    const int g = L >> 2, t4 = L & 3;

    float acc[4][2][4];
#pragma unroll
    for (int i = 0; i < 4; ++i)
#pragma unroll
        for (int j = 0; j < 2; ++j)
#pragma unroll
            for (int q = 0; q < 4; ++q) acc[i][j][q] = 0.f;

#define LOAD_STAGE(bufu, ch) do {                                                    \
        const size_t _co = (size_t)(ch) * 1024;                                      \
        cpa16((bufu) + dstA,      srcA + _co);                                       \
        cpa16((bufu) + dstA + 16, srcA + _co + 16);                                  \
        cpa16((bufu) + dstBR,      Gsrc + (size_t)(ch) * KCH);                       \
        cpa16((bufu) + dstBR + 16, Gsrc + (size_t)(ch) * KCH + 4);                   \
    } while (0)

#define CONV_STAGE(basep) do {                                                       \
        const char* _rp = (basep) + OF_BR + gr * BR_STRIDE + bq * 32;                \
        const float4 _v0 = *(const float4*)_rp;                                      \
        const float4 _v1 = *(const float4*)(_rp + 16);                               \
        char* _wp = (basep) + dstBF;                                                 \
        *(uint32_t*)(_wp + (gg8 * 4 + 0) * 8) = pack_hf2(_v0.x, _v0.y);              \
        *(uint32_t*)(_wp + (gg8 * 4 + 1) * 8) = pack_hf2(_v0.z, _v0.w);              \
        *(uint32_t*)(_wp + (gg8 * 4 + 2) * 8) = pack_hf2(_v1.x, _v1.y);              \
        *(uint32_t*)(_wp + (gg8 * 4 + 3) * 8) = pack_hf2(_v1.z, _v1.w);              \
    } while (0)

    LOAD_STAGE(sb, 0);
    asm volatile("cp.async.commit_group;" ::: "memory");
    LOAD_STAGE(sb + STG_SZ, 1);
    asm volatile("cp.async.commit_group;" ::: "memory");
    asm volatile("cp.async.wait_group 1;" ::: "memory");
    CONV_STAGE(sm);
    __syncthreads();

    int stg = 0;
    for (int t = 0; t < NCH; ++t) {
        const int s2 = (stg + 2 >= STAGES) ? stg + 2 - STAGES : stg + 2;
        const int s1 = (stg + 1 >= STAGES) ? stg + 1 - STAGES : stg + 1;

        if (t + 2 < NCH) LOAD_STAGE(sb + s2 * STG_SZ, t + 2);
        asm volatile("cp.async.commit_group;" ::: "memory");

        const char* ub = sm + stg * STG_SZ;
#pragma unroll
        for (int s = 0; s < 2; ++s) {
            uint2 bh[2];
#pragma unroll
            for (int j = 0; j < 2; ++j) {
                const char* pb = ub + OF_BF + (((wn * 2 + j) * 2 + s) * 256) + L * 8;
                bh[j] = *(const uint2*)pb;
            }
#pragma unroll
            for (int i = 0; i < 4; ++i) {
                const char* pa = ub + OF_A + ((wm * 4 + i) * 2 + s) * 512 + L * 16;
                const uint4 ahv = *(const uint4*)pa;
                const uint32_t ah[4] = {ahv.x, ahv.y, ahv.z, ahv.w};
#pragma unroll
                for (int j = 0; j < 2; ++j)
                    mma_hf(acc[i][j], ah, bh[j].x, bh[j].y);
            }
        }

        asm volatile("cp.async.wait_group 1;" ::: "memory");
        if (t + 1 < NCH) CONV_STAGE(sm + s1 * STG_SZ);
        __syncthreads();
        stg = s1;
    }

#pragma unroll
    for (int i = 0; i < 4; ++i) {
        const int m = mhalf * 128 + wm * 64 + i * 16 + g;
#pragma unroll
        for (int j = 0; j < 2; ++j) {
            const int col = n0 + wn * 16 + j * 8 + 2 * t4;
            if (col < DIM_G) {
                *(float2*)&C[(size_t)m * DIM_G + col] =
                    make_float2(acc[i][j][0], acc[i][j][1]);
                *(float2*)&C[(size_t)(m + 8) * DIM_G + col] =
                    make_float2(acc[i][j][2], acc[i][j][3]);
            }
        }
    }
#undef LOAD_STAGE
#undef CONV_STAGE
}

// ================== pipelined k-major fp32 GEMM, k-range parameterized, raw output ==================
__global__ void __launch_bounds__(256, 2)
gemm_kk(const float* __restrict__ AT, const float* __restrict__ Bk,
        float* __restrict__ Cbase, int cstride,   // C = Cbase + blockIdx.z * cstride
        int M, int N, int ktiles)                  // k-range: blockIdx.z*ktiles .. +ktiles
{
    __shared__ __align__(16) float As[4][8][128];
    __shared__ __align__(16) float Bs[4][8][128];
    const uint32_t as_b = smem_u32(As), bs_b = smem_u32(Bs);

    const int tid = threadIdx.x;
    const int tx = tid & 15, ty = tid >> 4;
    const int n0 = blockIdx.x * 128;
    const int m0 = blockIdx.y * 128;
    const int kt0 = blockIdx.z * ktiles;
    float* C = Cbase + (size_t)blockIdx.z * cstride;

    const int r = tid >> 5, c4 = (tid & 31) * 4;

#define LOADKK(s_, t_) do {                                                          \
        cpa16(as_b + (uint32_t)((((s_) * 8 + r) * 128 + c4) * 4),                    \
              AT + (size_t)((kt0 + (t_)) * 8 + r) * M + m0 + c4);                    \
        cpa16(bs_b + (uint32_t)((((s_) * 8 + r) * 128 + c4) * 4),                    \
              Bk + (size_t)((kt0 + (t_)) * 8 + r) * N + n0 + c4);                    \
    } while (0)

    LOADKK(0, 0); asm volatile("cp.async.commit_group;" ::: "memory");
    LOADKK(1, 1); asm volatile("cp.async.commit_group;" ::: "memory");
    LOADKK(2, 2); asm volatile("cp.async.commit_group;" ::: "memory");
    asm volatile("cp.async.wait_group 2;" ::: "memory");
    __syncthreads();

    unsigned long long acc[8][4];
#pragma unroll
    for (int i = 0; i < 8; ++i)
#pragma unroll
        for (int j = 0; j < 4; ++j) acc[i][j] = 0ull;

    for (int t = 0; t < ktiles; ++t) {
        if (t + 3 < ktiles) LOADKK((t + 3) & 3, t + 3);
        asm volatile("cp.async.commit_group;" ::: "memory");

        const int cur = t & 3;
#pragma unroll
        for (int kk = 0; kk < 8; ++kk) {
            const float4 av0 = *reinterpret_cast<const float4*>(&As[cur][kk][ty * 8]);
            const float4 av1 = *reinterpret_cast<const float4*>(&As[cur][kk][ty * 8 + 4]);
            const ulonglong2 bv0 = *reinterpret_cast<const ulonglong2*>(&Bs[cur][kk][tx * 8]);
            const ulonglong2 bv1 = *reinterpret_cast<const ulonglong2*>(&Bs[cur][kk][tx * 8 + 4]);
            const float a8[8] = {av0.x, av0.y, av0.z, av0.w, av1.x, av1.y, av1.z, av1.w};
#pragma unroll
            for (int i = 0; i < 8; ++i) {
                const unsigned long long aa = pk2(a8[i], a8[i]);
                fma2(acc[i][0], aa, bv0.x);
                fma2(acc[i][1], aa, bv0.y);
                fma2(acc[i][2], aa, bv1.x);
                fma2(acc[i][3], aa, bv1.y);
            }
        }
        asm volatile("cp.async.wait_group 2;" ::: "memory");
        __syncthreads();
    }

#pragma unroll
    for (int i = 0; i < 8; ++i) {
        const int m = m0 + ty * 8 + i;
#pragma unroll
        for (int j = 0; j < 4; ++j) {
            const int n = n0 + tx * 8 + j * 2;
            *reinterpret_cast<float2*>(&C[(size_t)m * N + n]) = upk2(acc[i][j]);
        }
    }
#undef LOADKK
}

// ---------------- combine W2 partials ----------------
__global__ void __launch_bounds__(256)
k_cw2(const float* __restrict__ P, float* __restrict__ W2) {
    const int i4 = (blockIdx.x * 256 + threadIdx.x) * 4;   // 576 blocks cover 589824
    if (i4 < DD) {
        float4 a = *(const float4*)&P[i4];
        float4 b = *(const float4*)&P[DD + i4];
        float4 c = *(const float4*)&P[2 * DD + i4];
        float4 d = *(const float4*)&P[3 * DD + i4];
        float4 v;
        v.x = a.x + b.x + c.x + d.x;
        v.y = a.y + b.y + c.y + d.y;
        v.z = a.z + b.z + c.z + d.z;
        v.w = a.w + b.w + c.w + d.w;
        *(float4*)&W2[i4] = v;
    }
}

// ---------------- combine PROJ partials -> exact A + fragment-packed fp16 ----------------
__global__ void __launch_bounds__(256)
k_combine(const float* __restrict__ P3a, const float* __restrict__ P3b,
          const float* __restrict__ bv,
          float* __restrict__ Aex, uint32_t* __restrict__ H)
{
    const int base = (blockIdx.x * 256 + threadIdx.x) * 6;
#pragma unroll
    for (int e = 0; e < 6; ++e) {
        const int p = base + e;                // pair index over 2048 x 384
        const int m = p / 384;
        const int n = (p - m * 384) * 2;
        const size_t off = (size_t)m * DIM_D + n;
        const float2 a = *(const float2*)&P3a[off];
        const float2 b = *(const float2*)&P3b[off];
        const float s = SCALE * g_w[m & 7];
        const float2 v = make_float2((a.x + b.x + bv[n])     * s,
                                     (a.y + b.y + bv[n + 1]) * s);
        *(float2*)&Aex[off] = v;
        const int bp = m >> 3;
        const int kd = (m & 7) * DIM_D + n;
        const int r = bp & 15, cc = kd & 15;
        const int word = (r >> 3) | (((cc >> 3) & 1) << 1);
        const int lane = ((r & 7) << 2) | ((cc >> 1) & 3);
        const size_t idx = (((size_t)(bp >> 4) * KT384 + (kd >> 4)) << 7)
                         + (lane << 2) + word;
        H[idx] = pack_hf2(v.x, v.y);
    }
}

// ---------------- transpose cQ (2048 x 768) -> cqT (768 x 2048) ----------------
__global__ void k_transpose(const float* __restrict__ in, float* __restrict__ out) {
    __shared__ float tile[32][33];
    const int x = blockIdx.x * 32 + threadIdx.x;
    const int y = blockIdx.y * 32 + threadIdx.y;
#pragma unroll
    for (int j = 0; j < 32; j += 8)
        tile[threadIdx.y + j][threadIdx.x] = in[(size_t)(y + j) * DIM_D + x];
    __syncthreads();
    const int x2 = blockIdx.y * 32 + threadIdx.x;
    const int y2 = blockIdx.x * 32 + threadIdx.y;
#pragma unroll
    for (int j = 0; j < 32; j += 8)
        out[(size_t)(y2 + j) * MQ + x2] = tile[threadIdx.x][threadIdx.y + j];
}

// ---------------- small vectors ----------------
__global__ void __launch_bounds__(256) k_vecs(const float* __restrict__ Wq,
                                              const float* __restrict__ Wk,
                                              const float* __restrict__ bq,
                                              const float* __restrict__ bk) {
    const int b = blockIdx.x;
    __shared__ float red[256];
    if (b < 12) {
        const bool isVk = b < 6;
        const int col = (isVk ? b : b - 6) * 128 + (threadIdx.x & 127);
        const int half = threadIdx.x >> 7;
        const float* Mt = isVk ? Wq : Wk;
        const float* vec = isVk ? bk : bq;
        float s = 0.f;
        for (int e = half; e < DIM_D; e += 2)
            s += Mt[(size_t)e * DIM_D + col] * vec[e];
        red[threadIdx.x] = s; __syncthreads();
        if (half == 0) {
            const float v = red[threadIdx.x] + red[threadIdx.x + 128];
            if (isVk) g_vk[col] = v; else g_bv[col] = v;
        }
    } else {
        float s = 0.f;
        for (int e = threadIdx.x; e < DIM_D; e += 256) s += bq[e] * bk[e];
        red[threadIdx.x] = s; __syncthreads();
        for (int o = 128; o > 0; o >>= 1) {
            if (threadIdx.x < o) red[threadIdx.x] += red[threadIdx.x + o];
            __syncthreads();
        }
        if (threadIdx.x == 0) g_bqk = red[0];
    }
}

__global__ void k_prep(const float* __restrict__ fw, float* __restrict__ tail, int wt) {
    if (threadIdx.x == 0) {
        float mx = fw[0];
        for (int k = 1; k < DIM_K; ++k) mx = fmaxf(mx, fw[k]);
        float e[DIM_K], s = 0.f;
        for (int k = 0; k < DIM_K; ++k) { e[k] = expf(fw[k] - mx); s += e[k]; }
        for (int k = 0; k < DIM_K; ++k) {
            const float w = e[k] / s;
            g_w[k] = w;
            if (wt) tail[k] = w;
        }
    }
}

__global__ void k_rowbias(const float* __restrict__ conf, const float* __restrict__ cQ) {
    const int bp = blockIdx.x, tid = threadIdx.x;
    __shared__ float red[256];
    float s = 0.f;
    for (int e = tid; e < DIM_D; e += 256) {
        const float v = g_vk[e];
#pragma unroll
        for (int k = 0; k < DIM_K; ++k)
            s += cQ[(size_t)(bp * 8 + k) * DIM_D + e] * v * (SCALE * g_w[k]);
    }
    red[tid] = s; __syncthreads();
    for (int off = 128; off > 0; off >>= 1) {
        if (tid < off) red[tid] += red[tid + off];
        __syncthreads();
    }
    if (tid == 0) {
        float cb = 0.f, bb = 0.f;
        for (int k = 0; k < DIM_K; ++k) {
            cb += logf(fmaxf(conf[bp * DIM_K + k], 1e-6f)) * g_w[k];
            bb += SCALE * g_w[k] * g_bqk;
        }
        g_rowbias[bp] = red[0] + bb + cb;
    }
}

// ---- exact top-200 with fp32 boundary rescue; adds rowbias on write ----
__global__ void __launch_bounds__(512) k_select(float* __restrict__ io,
                                                const float* __restrict__ Aex,
                                                const float* __restrict__ GF)
{
    const int row = blockIdx.x, tid = threadIdx.x;
    float* p = io + (size_t)row * DIM_G;
    const float rb = g_rowbias[row];

    float vals[40]; unsigned keys[40];
#pragma unroll
    for (int it = 0; it < 40; ++it) {
        const int j = tid + it * 512;
        float v = -1e30f; unsigned key = 0u;
        if (j < DIM_G) { v = p[j]; key = f2key(v); }
        vals[it] = v; keys[it] = key;
    }

    __shared__ int s_cnt, s_above, s_bandcnt, s_gt;
    __shared__ int   bj[BANDCAP];
    __shared__ float bex[BANDCAP];

    unsigned prefix = 0u;
    for (int b = 31; b >= 0; --b) {
        const unsigned cand = prefix | (1u << b);
        if (tid == 0) s_cnt = 0;
        __syncthreads();
        int c = 0;
#pragma unroll
        for (int it = 0; it < 40; ++it) c += (keys[it] >= cand);
        c = __reduce_add_sync(0xFFFFFFFFu, c);
        if ((tid & 31) == 0) atomicAdd(&s_cnt, c);
        __syncthreads();
        if (s_cnt >= TOPK_N) prefix = cand;
        __syncthreads();
    }
    const float tau = key2f(prefix);
    const float lo = tau - MARGIN, hi = tau + MARGIN;

    if (tid == 0) { s_above = 0; s_bandcnt = 0; }
    __syncthreads();
    {
        int c = 0;
#pragma unroll
        for (int it = 0; it < 40; ++it) c += (vals[it] > hi);
        c = __reduce_add_sync(0xFFFFFFFFu, c);
        if ((tid & 31) == 0) atomicAdd(&s_above, c);
    }
#pragma unroll
    for (int it = 0; it < 40; ++it) {
        const int j = tid + it * 512;
        const float v = vals[it];
        if (j < DIM_G && v >= lo && v <= hi) {
            const int s = atomicAdd(&s_bandcnt, 1);
            if (s < BANDCAP) bj[s] = j;
        }
    }
    __syncthreads();
    const int bn = min(s_bandcnt, BANDCAP);
    const int need = TOPK_N - s_above;

    const int wid = tid >> 5, lane = tid & 31;
    const float* Ar = Aex + (size_t)row * KD;
    for (int e = wid; e < bn; e += 16) {
        const float* Gr = GF + (size_t)bj[e] * KD;
        float s = 0.f;
        for (int d = lane; d < KD; d += 32) s = fmaf(Ar[d], Gr[d], s);
#pragma unroll
        for (int off = 16; off > 0; off >>= 1)
            s += __shfl_down_sync(0xFFFFFFFFu, s, off);
        if (lane == 0) bex[e] = s;
    }
    __syncthreads();

    unsigned kth = 0u;
    if (need > 0 && bn > 0) {
        unsigned pfx = 0u;
        for (int b = 31; b >= 0; --b) {
            const unsigned cand = pfx | (1u << b);
            if (tid == 0) s_cnt = 0;
            __syncthreads();
            int c = 0;
            for (int e = tid; e < bn; e += 512) c += (f2key(bex[e]) >= cand);
            c = __reduce_add_sync(0xFFFFFFFFu, c);
            if ((tid & 31) == 0) atomicAdd(&s_cnt, c);
            __syncthreads();
            if (s_cnt >= need) pfx = cand;
            __syncthreads();
        }
        kth = pfx;
    }

#pragma unroll
    for (int it = 0; it < 40; ++it) {
        const int j = tid + it * 512;
        if (j < DIM_G) {
            const float v = vals[it];
            if (v > hi)      p[j] = v + rb;
            else if (v < lo) p[j] = 0.f;
        }
    }
    for (int e = tid; e < bn; e += 512) p[bj[e]] = 0.f;
    if (tid == 0) s_gt = 0;
    __syncthreads();

    if (need > 0 && bn > 0) {
        int c = 0;
        for (int e = tid; e < bn; e += 512) c += (f2key(bex[e]) > kth);
        c = __reduce_add_sync(0xFFFFFFFFu, c);
        if ((tid & 31) == 0) atomicAdd(&s_gt, c);
        __syncthreads();
        const int gt = s_gt;
        for (int e = tid; e < bn; e += 512) {
            const unsigned k = f2key(bex[e]);
            bool keep = false;
            if (k > kth) keep = true;
            else if (k == kth) {
                int before = 0;
                for (int e2 = 0; e2 < e; ++e2) before += (f2key(bex[e2]) == kth);
                keep = (gt + before) < need;
            }
            if (keep) p[bj[e]] = bex[e] + rb;
        }
    }
}

// ---------------- launch ----------------
extern "C" void kernel_launch(void* const* d_in, const int* in_sizes, int n_in,
                              void* d_out, int out_size) {
    const float* cQ   = (const float*)d_in[0];
    const float* GF   = (const float*)d_in[1];
    const float* conf = (const float*)d_in[2];
    const float* Wq   = (const float*)d_in[3];
    const float* bq   = (const float*)d_in[4];
    const float* Wk   = (const float*)d_in[5];
    const float* bk   = (const float*)d_in[6];
    const float* fw   = (const float*)d_in[7];
    float* out = (float*)d_out;

    float *pCqT = nullptr, *pW2p = nullptr, *pW2 = nullptr, *pP3a = nullptr,
          *pP3b = nullptr, *pAe = nullptr, *pBv = nullptr;
    uint32_t* pA0 = nullptr;
    cudaGetSymbolAddress((void**)&pCqT, g_cqT);
    cudaGetSymbolAddress((void**)&pW2p, g_W2p);
    cudaGetSymbolAddress((void**)&pW2,  g_W2);
    cudaGetSymbolAddress((void**)&pP3a, g_P3a);
    cudaGetSymbolAddress((void**)&pP3b, g_P3b);
    cudaGetSymbolAddress((void**)&pAe,  g_A);
    cudaGetSymbolAddress((void**)&pA0,  g_A0);
    cudaGetSymbolAddress((void**)&pBv,  g_bv);

    cudaFuncSetAttribute(mma_main, cudaFuncAttributeMaxDynamicSharedMemorySize, SMEM_MAIN);

    const int BPG = BP * DIM_G;
    const int wt = (out_size >= BPG + DIM_K) ? 1 : 0;

    // 1) softmax(facet_weights)
    k_prep<<<1, 32>>>(fw, out + BPG, wt);

    // 2) cQ^T
    k_transpose<<<dim3(DIM_D / 32, MQ / 32), dim3(32, 8)>>>(cQ, pCqT);

    // 3) vk/bv/bqk
    k_vecs<<<13, 256>>>(Wq, Wk, bq, bk);

    // 4) W2 partials = Wq^T @ Wk, split-K 4 (144 CTAs)
    gemm_kk<<<dim3(DIM_D / 128, DIM_D / 128, 4), 256>>>(
        Wq, Wk, pW2p, DD, DIM_D, DIM_D, 24);

    // 5) W2 combine
    k_cw2<<<576, 256>>>(pW2p, pW2);

    // 6) PROJ partials = cQ @ W2, split-K 2 (192 CTAs)
    gemm_kk<<<dim3(DIM_D / 128, MQ / 128, 2), 256>>>(
        pCqT, pW2, pP3a, (int)(pP3b - pP3a), MQ, DIM_D, 48);

    // 7) combine: A = diag(s)(PROJ + bv) -> exact fp32 + fp16 plane
    k_combine<<<512, 256>>>(pP3a, pP3b, pBv, pAe, pA0);

    // 8) scores = fp16(A) . fp16(GF)^T  (M-split, 3 CTAs/SM)
    mma_main<<<dim3(2, NTY), 256, SMEM_MAIN>>>(pA0, GF, out);

    // 9) rowbias
    k_rowbias<<<BP, 256>>>(conf, cQ);

    // 10) exact top-200 with fp32 boundary rescue (+rowbias)
    k_select<<<BP, 512>>>(out, pAe, GF);
}